// round 9
// baseline (speedup 1.0000x reference)
#include <cuda_runtime.h>

#define Bsz 128
#define Hdim 256
#define Wdim 1024
#define N_HOLES 5
#define PROB 1.0f
#define HOLE_MINW (Wdim / 10)              // 102
#define HOLE_MINH (Hdim / 10)              // 25
#define N_TOTAL ((long long)Bsz * Hdim * Wdim)   // 33,554,432 floats
#define NHOLE_T (Bsz * N_HOLES)            // 640

#define GRID 592                           // 148 SMs * 4 -> all co-resident
#define NT 256

__device__ float g_partials[GRID];
__device__ float g_mean;
__device__ int   g_count = 0;              // last block resets -> replay-safe
__device__ int   g_epoch = 0;              // monotonic: bumps once per launch

// Fused kernel (best-measured base R5 + streaming cache hints):
//  phase 1: float4 grid-stride copy x->out with __ldcs/__stcs (evict-first:
//           x is read-once, out is write-once -- keep them out of L2)
//  sync:    ticket counter; last block reduces partials -> g_mean, bumps epoch
//  phase 2: all blocks stride the 640 holes, vectorized rect fill
__global__ void __launch_bounds__(NT, 4) fused_cutout_kernel(
    const float4* __restrict__ x, float4* __restrict__ out,
    const int* __restrict__ xs, const int* __restrict__ ys,
    const int* __restrict__ xs_w_raw, const int* __restrict__ ys_h_raw,
    const float* __restrict__ act_rand)
{
    // Read epoch before any block could possibly bump it (bump requires all
    // GRID tickets; ours comes later).
    const int epoch0 = *(volatile int*)&g_epoch;

    // ---- phase 1: streaming copy + reduce ----
    const long long n4 = N_TOTAL / 4;
    long long i = (long long)blockIdx.x * NT + threadIdx.x;
    const long long stride = (long long)GRID * NT;
    float s = 0.0f;
    #pragma unroll 4
    for (; i < n4; i += stride) {
        float4 v = __ldcs(&x[i]);
        __stcs(&out[i], v);
        s += (v.x + v.y) + (v.z + v.w);
    }

    #pragma unroll
    for (int o = 16; o > 0; o >>= 1)
        s += __shfl_down_sync(0xFFFFFFFFu, s, o);
    __shared__ float ws[8];
    const int lane = threadIdx.x & 31, warp = threadIdx.x >> 5;
    if (lane == 0) ws[warp] = s;
    __syncthreads();
    __shared__ int is_last;
    if (threadIdx.x == 0) {
        float v = ws[0];
        #pragma unroll
        for (int k = 1; k < 8; ++k) v += ws[k];
        g_partials[blockIdx.x] = v;
        __threadfence();
        int ticket = atomicAdd(&g_count, 1);
        is_last = (ticket == GRID - 1);
    }
    __syncthreads();

    if (is_last) {
        // fixed-order float reduction of GRID partials (deterministic)
        float s2 = 0.0f;
        for (int k = threadIdx.x; k < GRID; k += NT)
            s2 += g_partials[k];
        #pragma unroll
        for (int o = 16; o > 0; o >>= 1)
            s2 += __shfl_down_sync(0xFFFFFFFFu, s2, o);
        __shared__ float wf[8];
        if (lane == 0) wf[warp] = s2;
        __syncthreads();
        if (threadIdx.x == 0) {
            float t = wf[0];
            #pragma unroll
            for (int k = 1; k < 8; ++k) t += wf[k];
            g_mean = t * (1.0f / (float)N_TOTAL);
            g_count = 0;                   // reset for next replay
            __threadfence();
            *(volatile int*)&g_epoch = epoch0 + 1;   // release
        }
    }

    // ---- grid-wide sync: thread 0 spins, block follows ----
    if (threadIdx.x == 0) {
        while (*(volatile int*)&g_epoch == epoch0)
            __nanosleep(32);
    }
    __syncthreads();
    __threadfence();                       // acquire
    const float fill = *(volatile float*)&g_mean;
    const float4 f4 = make_float4(fill, fill, fill, fill);

    // ---- phase 2: fill holes (all blocks, strided) ----
    const int qx = threadIdx.x & 63;       // quad lane
    const int ry = threadIdx.x >> 6;       // row lane (0..3)

    for (int hole = blockIdx.x; hole < NHOLE_T; hole += GRID) {
        if (!(act_rand[hole] < PROB)) continue;
        const int b = hole / N_HOLES;

        const int hw = xs_w_raw[hole] + HOLE_MINW;
        const int hh = ys_h_raw[hole] + HOLE_MINH;
        const int cw = xs[hole], ch = ys[hole];
        const int x0 = min(max(cw - hw / 2, 0), Wdim - 2);
        const int x1 = min(max(cw + hw / 2, 1), Wdim - 1);
        const int y0 = min(max(ch - hh / 2, 0), Hdim - 2);
        const int y1 = min(max(ch + hh / 2, 1), Hdim - 1);

        const int a0 = (x0 + 3) & ~3;      // first aligned float index
        const int a1 = (x1 + 1) & ~3;      // exclusive aligned end
        const int nvec = (a1 - a0) >> 2;   // float4 interior count

        const int wl = x0 + qx;            // left-edge scalar (qx < 3)
        const bool do_l = (qx < 3) && (wl < a0);
        const int wr = a1 + (qx - 3);      // right-edge scalar (qx in [3,6))
        const bool do_r = (qx >= 3) && (qx < 6) && (wr <= x1);

        float* const base = (float*)out + (size_t)b * Hdim * Wdim + a0;
        for (int h = y0 + ry; h <= y1; h += 4) {
            float* const row = base + (size_t)h * Wdim;
            if (do_l) row[wl - a0] = fill;
            if (do_r) row[wr - a0] = fill;
            float4* const rowv = reinterpret_cast<float4*>(row);
            for (int q = qx; q < nvec; q += 64)
                __stcs(&rowv[q], f4);
        }
    }
}

extern "C" void kernel_launch(void* const* d_in, const int* in_sizes, int n_in,
                              void* d_out, int out_size) {
    const float* x        = (const float*)d_in[0];
    const int*   xs       = (const int*)d_in[1];
    const int*   ys       = (const int*)d_in[2];
    const int*   xs_w_raw = (const int*)d_in[3];
    const int*   ys_h_raw = (const int*)d_in[4];
    const float* act_rand = (const float*)d_in[5];
    float* out = (float*)d_out;

    fused_cutout_kernel<<<GRID, NT>>>((const float4*)x, (float4*)out,
                                      xs, ys, xs_w_raw, ys_h_raw, act_rand);
}

// round 10
// speedup vs baseline: 1.1032x; 1.1032x over previous
#include <cuda_runtime.h>

#define Bsz 128
#define Hdim 256
#define Wdim 1024
#define N_HOLES 5
#define PROB 1.0f
#define HOLE_MINW (Wdim / 10)              // 102
#define HOLE_MINH (Hdim / 10)              // 25
#define N_TOTAL ((long long)Bsz * Hdim * Wdim)   // 33,554,432 floats
#define NHOLE_T (Bsz * N_HOLES)            // 640

#define GRID 512                           // <= 592 resident @ occ 4
#define NT 256
#define TOTT (GRID * NT)                   // 131,072 threads
#define JB 8                               // front-batched LDG.128 per iter
#define KITER 8                            // (N_TOTAL/4) / (TOTT*JB) == 8

__device__ float g_partials[GRID];
__device__ float g_mean;
__device__ int   g_count = 0;              // last block resets -> replay-safe
__device__ int   g_epoch = 0;              // monotonic: bumps once per launch

// Fused kernel: occ-4 regime (best measured) + 8-deep float4 MLP batching.
//  phase 1: 8 iters, each = 8 batched LDG.128 then 8 STG.128 (+sum)
//  sync:    ticket counter; last block reduces partials -> g_mean, bumps epoch
//  phase 2: all blocks stride the 640 holes, vectorized rect fill
__global__ void __launch_bounds__(NT, 4) fused_cutout_kernel(
    const float4* __restrict__ x, float4* __restrict__ out,
    const int* __restrict__ xs, const int* __restrict__ ys,
    const int* __restrict__ xs_w_raw, const int* __restrict__ ys_h_raw,
    const float* __restrict__ act_rand)
{
    // Read epoch before any block could possibly bump it (bump requires all
    // GRID tickets; ours comes later).
    const int epoch0 = *(volatile int*)&g_epoch;

    // ---- phase 1: copy + reduce, 8 x 128B loads in flight per thread ----
    const int tg = blockIdx.x * NT + threadIdx.x;
    float s = 0.0f;
    #pragma unroll 1
    for (int k = 0; k < KITER; ++k) {
        const long long b0 = (long long)k * (JB * (long long)TOTT) + tg;
        float4 v[JB];
        #pragma unroll
        for (int j = 0; j < JB; ++j)
            v[j] = x[b0 + (long long)j * TOTT];
        #pragma unroll
        for (int j = 0; j < JB; ++j) {
            s += (v[j].x + v[j].y) + (v[j].z + v[j].w);
            out[b0 + (long long)j * TOTT] = v[j];
        }
    }

    #pragma unroll
    for (int o = 16; o > 0; o >>= 1)
        s += __shfl_down_sync(0xFFFFFFFFu, s, o);
    __shared__ float ws[8];
    const int lane = threadIdx.x & 31, warp = threadIdx.x >> 5;
    if (lane == 0) ws[warp] = s;
    __syncthreads();
    __shared__ int is_last;
    if (threadIdx.x == 0) {
        float v = ws[0];
        #pragma unroll
        for (int k = 1; k < 8; ++k) v += ws[k];
        g_partials[blockIdx.x] = v;
        __threadfence();
        int ticket = atomicAdd(&g_count, 1);
        is_last = (ticket == GRID - 1);
    }
    __syncthreads();

    if (is_last) {
        // fixed-order float reduction of GRID partials (deterministic)
        float s2 = 0.0f;
        for (int k = threadIdx.x; k < GRID; k += NT)
            s2 += g_partials[k];
        #pragma unroll
        for (int o = 16; o > 0; o >>= 1)
            s2 += __shfl_down_sync(0xFFFFFFFFu, s2, o);
        __shared__ float wf[8];
        if (lane == 0) wf[warp] = s2;
        __syncthreads();
        if (threadIdx.x == 0) {
            float t = wf[0];
            #pragma unroll
            for (int k = 1; k < 8; ++k) t += wf[k];
            g_mean = t * (1.0f / (float)N_TOTAL);
            g_count = 0;                   // reset for next replay
            __threadfence();
            *(volatile int*)&g_epoch = epoch0 + 1;   // release
        }
    }

    // ---- grid-wide sync: thread 0 spins, block follows ----
    if (threadIdx.x == 0) {
        while (*(volatile int*)&g_epoch == epoch0)
            __nanosleep(32);
    }
    __syncthreads();
    __threadfence();                       // acquire
    const float fill = *(volatile float*)&g_mean;
    const float4 f4 = make_float4(fill, fill, fill, fill);

    // ---- phase 2: fill holes (all blocks, strided) ----
    const int qx = threadIdx.x & 63;       // quad lane
    const int ry = threadIdx.x >> 6;       // row lane (0..3)

    for (int hole = blockIdx.x; hole < NHOLE_T; hole += GRID) {
        if (!(act_rand[hole] < PROB)) continue;
        const int b = hole / N_HOLES;

        const int hw = xs_w_raw[hole] + HOLE_MINW;
        const int hh = ys_h_raw[hole] + HOLE_MINH;
        const int cw = xs[hole], ch = ys[hole];
        const int x0 = min(max(cw - hw / 2, 0), Wdim - 2);
        const int x1 = min(max(cw + hw / 2, 1), Wdim - 1);
        const int y0 = min(max(ch - hh / 2, 0), Hdim - 2);
        const int y1 = min(max(ch + hh / 2, 1), Hdim - 1);

        const int a0 = (x0 + 3) & ~3;      // first aligned float index
        const int a1 = (x1 + 1) & ~3;      // exclusive aligned end
        const int nvec = (a1 - a0) >> 2;   // float4 interior count

        const int wl = x0 + qx;            // left-edge scalar (qx < 3)
        const bool do_l = (qx < 3) && (wl < a0);
        const int wr = a1 + (qx - 3);      // right-edge scalar (qx in [3,6))
        const bool do_r = (qx >= 3) && (qx < 6) && (wr <= x1);

        float* const base = (float*)out + (size_t)b * Hdim * Wdim + a0;
        for (int h = y0 + ry; h <= y1; h += 4) {
            float* const row = base + (size_t)h * Wdim;
            if (do_l) row[wl - a0] = fill;
            if (do_r) row[wr - a0] = fill;
            float4* const rowv = reinterpret_cast<float4*>(row);
            for (int q = qx; q < nvec; q += 64)
                rowv[q] = f4;
        }
    }
}

extern "C" void kernel_launch(void* const* d_in, const int* in_sizes, int n_in,
                              void* d_out, int out_size) {
    const float* x        = (const float*)d_in[0];
    const int*   xs       = (const int*)d_in[1];
    const int*   ys       = (const int*)d_in[2];
    const int*   xs_w_raw = (const int*)d_in[3];
    const int*   ys_h_raw = (const int*)d_in[4];
    const float* act_rand = (const float*)d_in[5];
    float* out = (float*)d_out;

    fused_cutout_kernel<<<GRID, NT>>>((const float4*)x, (float4*)out,
                                      xs, ys, xs_w_raw, ys_h_raw, act_rand);
}

// round 11
// speedup vs baseline: 1.1499x; 1.0424x over previous
#include <cuda_runtime.h>

#define Bsz 128
#define Hdim 256
#define Wdim 1024
#define N_HOLES 5
#define PROB 1.0f
#define HOLE_MINW (Wdim / 10)              // 102
#define HOLE_MINH (Hdim / 10)              // 25
#define N_TOTAL ((long long)Bsz * Hdim * Wdim)   // 33,554,432 floats
#define NHOLE_T (Bsz * N_HOLES)            // 640

#define GRID 592                           // 148 SMs * 4 -> perfectly balanced
#define NT 256
#define TOTT (GRID * NT)                   // 151,552 threads
#define N4 (N_TOTAL / 4)                   // 8,388,608 float4
// decomposition: 6 iters of 8 batched + 1 iter of 7 batched + 1 predicated
// 6*8*TOTT + 7*TOTT = 55*TOTT = 8,335,360 ; remainder 53,248 (< TOTT)

__device__ float g_partials[GRID];
__device__ float g_mean;
__device__ int   g_count = 0;              // last block resets -> replay-safe
__device__ int   g_epoch = 0;              // monotonic: bumps once per launch

__global__ void __launch_bounds__(NT, 4) fused_cutout_kernel(
    const float4* __restrict__ x, float4* __restrict__ out,
    const int* __restrict__ xs, const int* __restrict__ ys,
    const int* __restrict__ xs_w_raw, const int* __restrict__ ys_h_raw,
    const float* __restrict__ act_rand)
{
    // Read epoch before any block could possibly bump it (bump requires all
    // GRID tickets; ours comes later).
    const int epoch0 = *(volatile int*)&g_epoch;

    const int tg = blockIdx.x * NT + threadIdx.x;
    float s = 0.0f;

    // ---- phase 1a: 6 iterations of 8 front-batched LDG.128 ----
    #pragma unroll 1
    for (int k = 0; k < 6; ++k) {
        const long long b0 = (long long)k * (8 * (long long)TOTT) + tg;
        float4 v[8];
        #pragma unroll
        for (int j = 0; j < 8; ++j)
            v[j] = x[b0 + (long long)j * TOTT];
        #pragma unroll
        for (int j = 0; j < 8; ++j) {
            s += (v[j].x + v[j].y) + (v[j].z + v[j].w);
            out[b0 + (long long)j * TOTT] = v[j];
        }
    }
    // ---- phase 1b: 1 iteration of 7 batched ----
    {
        const long long b0 = 48LL * TOTT + tg;
        float4 v[7];
        #pragma unroll
        for (int j = 0; j < 7; ++j)
            v[j] = x[b0 + (long long)j * TOTT];
        #pragma unroll
        for (int j = 0; j < 7; ++j) {
            s += (v[j].x + v[j].y) + (v[j].z + v[j].w);
            out[b0 + (long long)j * TOTT] = v[j];
        }
    }
    // ---- phase 1c: predicated final element ----
    {
        const long long i = 55LL * TOTT + tg;
        if (i < N4) {
            float4 v = x[i];
            s += (v.x + v.y) + (v.z + v.w);
            out[i] = v;
        }
    }

    #pragma unroll
    for (int o = 16; o > 0; o >>= 1)
        s += __shfl_down_sync(0xFFFFFFFFu, s, o);
    __shared__ float ws[8];
    const int lane = threadIdx.x & 31, warp = threadIdx.x >> 5;
    if (lane == 0) ws[warp] = s;
    __syncthreads();
    __shared__ int is_last;
    if (threadIdx.x == 0) {
        float v = ws[0];
        #pragma unroll
        for (int k = 1; k < 8; ++k) v += ws[k];
        g_partials[blockIdx.x] = v;
        __threadfence();
        int ticket = atomicAdd(&g_count, 1);
        is_last = (ticket == GRID - 1);
    }
    __syncthreads();

    if (is_last) {
        // fixed-order float reduction of GRID partials (deterministic)
        float s2 = 0.0f;
        for (int k = threadIdx.x; k < GRID; k += NT)
            s2 += g_partials[k];
        #pragma unroll
        for (int o = 16; o > 0; o >>= 1)
            s2 += __shfl_down_sync(0xFFFFFFFFu, s2, o);
        __shared__ float wf[8];
        if (lane == 0) wf[warp] = s2;
        __syncthreads();
        if (threadIdx.x == 0) {
            float t = wf[0];
            #pragma unroll
            for (int k = 1; k < 8; ++k) t += wf[k];
            g_mean = t * (1.0f / (float)N_TOTAL);
            g_count = 0;                   // reset for next replay
            __threadfence();
            *(volatile int*)&g_epoch = epoch0 + 1;   // release
        }
    }

    // ---- grid-wide sync: thread 0 spins, block follows ----
    if (threadIdx.x == 0) {
        while (*(volatile int*)&g_epoch == epoch0)
            __nanosleep(32);
    }
    __syncthreads();
    __threadfence();                       // acquire
    const float fill = *(volatile float*)&g_mean;
    const float4 f4 = make_float4(fill, fill, fill, fill);

    // ---- phase 2: fill holes (all blocks, strided) ----
    const int qx = threadIdx.x & 63;       // quad lane
    const int ry = threadIdx.x >> 6;       // row lane (0..3)

    for (int hole = blockIdx.x; hole < NHOLE_T; hole += GRID) {
        if (!(act_rand[hole] < PROB)) continue;
        const int b = hole / N_HOLES;

        const int hw = xs_w_raw[hole] + HOLE_MINW;
        const int hh = ys_h_raw[hole] + HOLE_MINH;
        const int cw = xs[hole], ch = ys[hole];
        const int x0 = min(max(cw - hw / 2, 0), Wdim - 2);
        const int x1 = min(max(cw + hw / 2, 1), Wdim - 1);
        const int y0 = min(max(ch - hh / 2, 0), Hdim - 2);
        const int y1 = min(max(ch + hh / 2, 1), Hdim - 1);

        const int a0 = (x0 + 3) & ~3;      // first aligned float index
        const int a1 = (x1 + 1) & ~3;      // exclusive aligned end
        const int nvec = (a1 - a0) >> 2;   // float4 interior count

        const int wl = x0 + qx;            // left-edge scalar (qx < 3)
        const bool do_l = (qx < 3) && (wl < a0);
        const int wr = a1 + (qx - 3);      // right-edge scalar (qx in [3,6))
        const bool do_r = (qx >= 3) && (qx < 6) && (wr <= x1);

        float* const base = (float*)out + (size_t)b * Hdim * Wdim + a0;
        for (int h = y0 + ry; h <= y1; h += 4) {
            float* const row = base + (size_t)h * Wdim;
            if (do_l) row[wl - a0] = fill;
            if (do_r) row[wr - a0] = fill;
            float4* const rowv = reinterpret_cast<float4*>(row);
            for (int q = qx; q < nvec; q += 64)
                rowv[q] = f4;
        }
    }
}

extern "C" void kernel_launch(void* const* d_in, const int* in_sizes, int n_in,
                              void* d_out, int out_size) {
    const float* x        = (const float*)d_in[0];
    const int*   xs       = (const int*)d_in[1];
    const int*   ys       = (const int*)d_in[2];
    const int*   xs_w_raw = (const int*)d_in[3];
    const int*   ys_h_raw = (const int*)d_in[4];
    const float* act_rand = (const float*)d_in[5];
    float* out = (float*)d_out;

    fused_cutout_kernel<<<GRID, NT>>>((const float4*)x, (float4*)out,
                                      xs, ys, xs_w_raw, ys_h_raw, act_rand);
}